// round 1
// baseline (speedup 1.0000x reference)
#include <cuda_runtime.h>

// loss = 0.5 * mean( (tw[b,j] * (output[b,j,hw] - target[b,j,hw]))^2 )
// B=256, J=17, HW=64*48=3072  ->  N = 13,369,344 floats, N4 = 3,342,336 float4
// tw has B*J = 4352 entries; each covers 768 consecutive float4s.

#define N_ELEMS   13369344
#define N4        3342336
#define F4_PER_BJ 768
#define NBLOCKS   1184      // 148 SMs * 8
#define NTHREADS  256

__device__ float g_partials[NBLOCKS];

__global__ __launch_bounds__(NTHREADS) void wmse_partial_kernel(
    const float4* __restrict__ out4,
    const float4* __restrict__ tgt4,
    const float*  __restrict__ tw)
{
    const int tid    = threadIdx.x;
    const int stride = gridDim.x * blockDim.x;
    int i = blockIdx.x * blockDim.x + tid;

    float acc = 0.0f;
    for (; i < N4; i += stride) {
        const float4 o = out4[i];
        const float4 t = tgt4[i];
        const float  w = tw[i / F4_PER_BJ];   // L2/L1-resident, 4352 entries
        float d0 = (o.x - t.x) * w;
        float d1 = (o.y - t.y) * w;
        float d2 = (o.z - t.z) * w;
        float d3 = (o.w - t.w) * w;
        acc += d0 * d0 + d1 * d1 + d2 * d2 + d3 * d3;
    }

    // warp reduce
    #pragma unroll
    for (int off = 16; off > 0; off >>= 1)
        acc += __shfl_down_sync(0xFFFFFFFFu, acc, off);

    __shared__ float warp_sums[NTHREADS / 32];
    if ((tid & 31) == 0) warp_sums[tid >> 5] = acc;
    __syncthreads();

    if (tid < NTHREADS / 32) {
        float v = warp_sums[tid];
        #pragma unroll
        for (int off = (NTHREADS / 64); off > 0; off >>= 1)
            v += __shfl_down_sync(0xFFFFFFFFu, v, off);
        if (tid == 0) g_partials[blockIdx.x] = v;
    }
}

__global__ __launch_bounds__(256) void wmse_final_kernel(float* __restrict__ out)
{
    const int tid = threadIdx.x;
    double acc = 0.0;
    for (int i = tid; i < NBLOCKS; i += 256)
        acc += (double)g_partials[i];

    #pragma unroll
    for (int off = 16; off > 0; off >>= 1)
        acc += __shfl_down_sync(0xFFFFFFFFu, acc, off);

    __shared__ double warp_sums[8];
    if ((tid & 31) == 0) warp_sums[tid >> 5] = acc;
    __syncthreads();

    if (tid == 0) {
        double total = 0.0;
        #pragma unroll
        for (int w = 0; w < 8; w++) total += warp_sums[w];
        out[0] = (float)(0.5 * total / (double)N_ELEMS);
    }
}

extern "C" void kernel_launch(void* const* d_in, const int* in_sizes, int n_in,
                              void* d_out, int out_size)
{
    const float4* out4 = (const float4*)d_in[0];
    const float4* tgt4 = (const float4*)d_in[1];
    const float*  tw   = (const float*)d_in[2];
    float* out = (float*)d_out;

    wmse_partial_kernel<<<NBLOCKS, NTHREADS>>>(out4, tgt4, tw);
    wmse_final_kernel<<<1, 256>>>(out);
}